// round 1
// baseline (speedup 1.0000x reference)
#include <cuda_runtime.h>
#include <cuda_bf16.h>

// LIF scan, chunk-parallel with cold-start warm-up.
//   i_t = LEAK_I*i_{t-1} + w*x_t
//   v_t = LEAK_V*v_{t-1}*(1-s_{t-1}) + i_t
//   s_t = (v_t - 1 > 0)
// State memory decays (0.9^t for v, (6/7)^t for i) and every spike resets v
// exactly, so a chunk warmed up from (0,0,0) over W=512 steps converges to the
// true trajectory (sub-ulp after ~130 steps, bitwise after the first common
// spike). Arithmetic replicates the reference op-for-op in f32 (no FMA
// contraction); (1-s) in {0,1} makes the reset multiply an exact select.

#define CHUNK_L 512
#define WARM_W  512

__device__ __forceinline__ void lif_step(float xt, float w, float LI, float LV,
                                         float& s, float& v, float& i) {
    float wx = __fmul_rn(w, xt);
    i = __fadd_rn(__fmul_rn(LI, i), wx);
    float lv = __fmul_rn(LV, v);
    lv = (s != 0.0f) ? 0.0f : lv;       // exact: (LV*v)*(1-s) with s in {0,1}
    v = __fadd_rn(lv, i);
    s = (v > 1.0f) ? 1.0f : 0.0f;       // Heaviside(v - 1) with strict >
}

__global__ void __launch_bounds__(64)
lif_scan_kernel(const float* __restrict__ x,
                const float* __restrict__ state0,
                const float* __restrict__ wptr,
                float* __restrict__ out,
                int T, int write_states) {
    const float LI = (float)(1.0 - 1.0 / 7.0);    // 0.857142857...f
    const float LV = (float)(1.0 - 1.0 / 10.0);   // 0.9f

    long long nchunks = ((long long)T + CHUNK_L - 1) / CHUNK_L;
    long long c = (long long)blockIdx.x * blockDim.x + threadIdx.x;
    if (c >= nchunks) return;

    long long start = c * CHUNK_L;
    long long end = start + CHUNK_L;
    if (end > T) end = T;

    float w = wptr[0];
    float s, v, i;

    if (c == 0) {
        s = state0[0]; v = state0[1]; i = state0[2];
    } else {
        // Cold-start warm-up: start-W >= 0 guaranteed (start >= CHUNK_L >= WARM_W)
        s = 0.0f; v = 0.0f; i = 0.0f;
        const float4* xw = (const float4*)(x + (start - WARM_W));
        #pragma unroll 8
        for (int j = 0; j < WARM_W / 4; ++j) {
            float4 q = xw[j];
            lif_step(q.x, w, LI, LV, s, v, i);
            lif_step(q.y, w, LI, LV, s, v, i);
            lif_step(q.z, w, LI, LV, s, v, i);
            lif_step(q.w, w, LI, LV, s, v, i);
        }
    }

    float* outs = out + start;                       // outputs[t]
    float* outv = out + (long long)T + 3 * start;    // states[t, 0..2]
    int L  = (int)(end - start);
    int L4 = L & ~3;

    // Vectorized main loop: float4 x-loads, float4 stores (all offsets are
    // multiples of 4 floats: start % 512 == 0, T % 4 == 0, 3*start % 4 == 0).
    for (int j = 0; j < L4; j += 4) {
        float4 q = *(const float4*)(x + start + j);
        float4 sb, a, b, cv;
        lif_step(q.x, w, LI, LV, s, v, i); sb.x = s; a.x  = s; a.y  = v; a.z  = i;
        lif_step(q.y, w, LI, LV, s, v, i); sb.y = s; a.w  = s; b.x  = v; b.y  = i;
        lif_step(q.z, w, LI, LV, s, v, i); sb.z = s; b.z  = s; b.w  = v; cv.x = i;
        lif_step(q.w, w, LI, LV, s, v, i); sb.w = s; cv.y = s; cv.z = v; cv.w = i;

        *(float4*)(outs + j) = sb;
        if (write_states) {
            float4* ov = (float4*)(outv + 3 * j);
            ov[0] = a; ov[1] = b; ov[2] = cv;
        }
    }
    // Scalar tail (only if T not a multiple of 4 within the last chunk)
    for (int j = L4; j < L; ++j) {
        lif_step(x[start + j], w, LI, LV, s, v, i);
        outs[j] = s;
        if (write_states) {
            outv[3 * j + 0] = s;
            outv[3 * j + 1] = v;
            outv[3 * j + 2] = i;
        }
    }
}

extern "C" void kernel_launch(void* const* d_in, const int* in_sizes, int n_in,
                              void* d_out, int out_size) {
    const float* x  = (const float*)d_in[0];   // (T, 1) float32
    const float* st = (const float*)d_in[1];   // (3, 1) float32 [s, v, i]
    const float* w  = (const float*)d_in[2];   // (1, 1) float32
    float* out = (float*)d_out;                // [outputs (T) | states (3T)]

    int T = in_sizes[0];
    int write_states = ((long long)out_size >= 4LL * T) ? 1 : 0;

    long long nchunks = ((long long)T + CHUNK_L - 1) / CHUNK_L;
    int threads = 64;
    int blocks = (int)((nchunks + threads - 1) / threads);
    lif_scan_kernel<<<blocks, threads>>>(x, st, w, out, T, write_states);
}